// round 10
// baseline (speedup 1.0000x reference)
#include <cuda_runtime.h>
#include <cuda_fp16.h>
#include <cstdint>

#define N_NODES 100000
#define N_EDGES 20000
#define NNZ     800000
#define D       128

// Scan tiling
#define SCAN_TPB   256
#define SCAN_PER   8
#define SCAN_CHUNK (SCAN_TPB * SCAN_PER)                      // 2048
#define NB1 ((N_EDGES + SCAN_CHUNK - 1) / SCAN_CHUNK)         // 10
#define NB2 ((N_NODES + SCAN_CHUNK - 1) / SCAN_CHUNK)         // 49
#define NBT (NB1 + NB2)                                       // 59

// ---------------------------------------------------------------------------
// Device-global scratch (allocation-free rule)
// ---------------------------------------------------------------------------
__device__ __align__(16) uint2 g_XH [N_NODES * 32]; // X in fp16 (2x half2/lane), 25.6 MB
__device__ __align__(16) uint2 g_XeH[N_EDGES * 32]; // Xe in fp16, 5.12 MB
__device__ __align__(16) float g_Xv[N_NODES * D];   // 51.2 MB (Xi)
__device__ __align__(16) float2 g_Wp[64 * 128];     // packed tf32 B fragments, 64 KB

__device__ int g1_cnt[N_EDGES];
__device__ int g1_off[N_EDGES + 1];
__device__ int g1_cur[N_EDGES];
__device__ int g1_idx[NNZ];
__device__ int g2_cnt[N_NODES];
__device__ int g2_off[N_NODES + 1];
__device__ int g2_cur[N_NODES];
__device__ int g2_idx[NNZ];

__device__ int g_thr_excl[NBT * SCAN_TPB];
__device__ int g_blk_sum[NBT];

// ---------------------------------------------------------------------------
// helpers
// ---------------------------------------------------------------------------
__device__ __forceinline__ uint32_t h2_to_u32(__half2 h) {
    return *reinterpret_cast<uint32_t*>(&h);
}
__device__ __forceinline__ __half2 u32_to_h2(uint32_t u) {
    return *reinterpret_cast<__half2*>(&u);
}
__device__ __forceinline__ uint32_t f2tf32(float f) {
    uint32_t r;
    asm("cvt.rna.tf32.f32 %0, %1;" : "=r"(r) : "f"(f));
    return r;
}
__device__ __forceinline__ void acc_h(float4& acc, uint2 r) {
    float2 f0 = __half22float2(u32_to_h2(r.x));
    float2 f1 = __half22float2(u32_to_h2(r.y));
    acc.x += f0.x; acc.y += f0.y; acc.z += f1.x; acc.w += f1.y;
}

// ---------------------------------------------------------------------------
// Prep: X->fp16 conversion + zero counters + W prep (single launch)
// ---------------------------------------------------------------------------
#define CONV_BLKS (N_NODES * 32 / 256)           // 12500
#define ZERO_BLKS ((N_NODES + 255) / 256)        // 391
#define WPREP_BLKS 32

__global__ void prep_kernel(const float4* __restrict__ X4,
                            const float* __restrict__ W) {
    const int b = blockIdx.x;
    if (b < CONV_BLKS) {
        int i = b * 256 + threadIdx.x;           // uint2 slot
        float4 v = __ldg(X4 + i);
        uint2 o;
        o.x = h2_to_u32(__floats2half2_rn(v.x, v.y));
        o.y = h2_to_u32(__floats2half2_rn(v.z, v.w));
        g_XH[i] = o;
    } else if (b < CONV_BLKS + ZERO_BLKS) {
        int i = (b - CONV_BLKS) * 256 + threadIdx.x;
        if (i < N_EDGES) g1_cnt[i] = 0;
        if (i < N_NODES) g2_cnt[i] = 0;
    } else {
        int p = (b - CONV_BLKS - ZERO_BLKS) * 256 + threadIdx.x;  // 8192 total
        if (p < 64 * 128) {
            int n = p & 127;
            int tig = (p >> 7) & 3;
            int kk = p >> 9;
            float w0 = __ldg(W + n * 128 + kk * 8 + tig);
            float w1 = __ldg(W + n * 128 + kk * 8 + tig + 4);
            float2 o;
            o.x = __uint_as_float(f2tf32(w0));
            o.y = __uint_as_float(f2tf32(w1));
            g_Wp[p] = o;
        }
    }
}

// ---------------------------------------------------------------------------
// Histogram, both graphs (int4-vectorized)
// ---------------------------------------------------------------------------
__global__ void hist_kernel(const int4* __restrict__ g1d4,
                            const int4* __restrict__ g2d4) {
    int i = blockIdx.x * blockDim.x + threadIdx.x;
    if (i >= NNZ / 4) return;
    int4 d1 = __ldg(g1d4 + i);
    atomicAdd(&g1_cnt[d1.x], 1);
    atomicAdd(&g1_cnt[d1.y], 1);
    atomicAdd(&g1_cnt[d1.z], 1);
    atomicAdd(&g1_cnt[d1.w], 1);
    int4 d2 = __ldg(g2d4 + i);
    atomicAdd(&g2_cnt[d2.x], 1);
    atomicAdd(&g2_cnt[d2.y], 1);
    atomicAdd(&g2_cnt[d2.z], 1);
    atomicAdd(&g2_cnt[d2.w], 1);
}

// Phase A: per-block partial scan.
__global__ void scanA_kernel() {
    const int bid = blockIdx.x;
    const int t = threadIdx.x;
    const int* cnt; int n, lbase;
    if (bid < NB1) { cnt = g1_cnt; n = N_EDGES; lbase = bid * SCAN_CHUNK; }
    else           { cnt = g2_cnt; n = N_NODES; lbase = (bid - NB1) * SCAN_CHUNK; }

    int s = 0;
    const int i0 = lbase + t * SCAN_PER;
#pragma unroll
    for (int k = 0; k < SCAN_PER; k++) {
        int i = i0 + k;
        s += (i < n) ? cnt[i] : 0;
    }

    const int lane = t & 31, wid = t >> 5;
    int v = s;
#pragma unroll
    for (int o = 1; o < 32; o <<= 1) {
        int u = __shfl_up_sync(0xffffffffu, v, o);
        if (lane >= o) v += u;
    }
    __shared__ int ws[8];
    if (lane == 31) ws[wid] = v;
    __syncthreads();
    if (t < 8) {
        int w = ws[t];
#pragma unroll
        for (int o = 1; o < 8; o <<= 1) {
            int u = __shfl_up_sync(0xffu, w, o);
            if (t >= o) w += u;
        }
        ws[t] = w;
    }
    __syncthreads();

    int excl = v - s + (wid ? ws[wid - 1] : 0);
    g_thr_excl[bid * SCAN_TPB + t] = excl;
    if (t == SCAN_TPB - 1) g_blk_sum[bid] = excl + s;
}

// Phase C (fused B).
__global__ void scanC_kernel() {
    __shared__ int be[NBT];
    __shared__ int wtot;
    const int bid = blockIdx.x;
    const int t = threadIdx.x;

    if (t < 64) {
        int v = (t < NBT) ? g_blk_sum[t] : 0;
        const int lane = t & 31;
        int s = v;
#pragma unroll
        for (int o = 1; o < 32; o <<= 1) {
            int u = __shfl_up_sync(0xffffffffu, s, o);
            if (lane >= o) s += u;
        }
        if (t == 31) wtot = s;
        if (t < NBT) be[t] = s - v;
    }
    __syncthreads();
    if (t >= 32 && t < 64 && t < NBT) be[t] += wtot;
    __syncthreads();
    if (t < NBT && t >= NB1) be[t] -= NNZ;
    __syncthreads();

    const int* cnt; int* off; int* cur; int n, lbase;
    if (bid < NB1) { cnt = g1_cnt; off = g1_off; cur = g1_cur; n = N_EDGES; lbase = bid * SCAN_CHUNK; }
    else           { cnt = g2_cnt; off = g2_off; cur = g2_cur; n = N_NODES; lbase = (bid - NB1) * SCAN_CHUNK; }

    int base = be[bid] + g_thr_excl[bid * SCAN_TPB + t];
    const int i0 = lbase + t * SCAN_PER;
#pragma unroll
    for (int k = 0; k < SCAN_PER; k++) {
        int i = i0 + k;
        if (i < n) {
            off[i] = base;
            cur[i] = base;
            base += cnt[i];
        }
    }
    if (bid == 0 && t == 0) {
        g1_off[N_EDGES] = NNZ;
        g2_off[N_NODES] = NNZ;
    }
}

// Fill, both graphs (int2-vectorized)
__global__ void fill_kernel(const int2* __restrict__ g1s2, const int2* __restrict__ g1d2,
                            const int2* __restrict__ g2s2, const int2* __restrict__ g2d2) {
    int i = blockIdx.x * blockDim.x + threadIdx.x;
    if (i >= NNZ / 2) return;
    int2 s1 = __ldg(g1s2 + i);
    int2 d1 = __ldg(g1d2 + i);
    int p0 = atomicAdd(&g1_cur[d1.x], 1);
    g1_idx[p0] = s1.x;
    int p1 = atomicAdd(&g1_cur[d1.y], 1);
    g1_idx[p1] = s1.y;
    int2 s2 = __ldg(g2s2 + i);
    int2 d2 = __ldg(g2d2 + i);
    int q0 = atomicAdd(&g2_cur[d2.x], 1);
    g2_idx[q0] = s2.x;
    int q1 = atomicAdd(&g2_cur[d2.y], 1);
    g2_idx[q1] = s2.y;
}

// ---------------------------------------------------------------------------
// SpMM 1: XeH[e] = fp16( degE[e] * sum XH[s] )   (warp/edge, fp16 gather, u8)
// ---------------------------------------------------------------------------
__global__ void spmm1_kernel(const float* __restrict__ degE) {
    int e = (blockIdx.x * blockDim.x + threadIdx.x) >> 5;
    if (e >= N_EDGES) return;
    int lane = threadIdx.x & 31;
    int beg = g1_off[e], end = g1_off[e + 1];

    float4 acc = make_float4(0.f, 0.f, 0.f, 0.f);
    int j = beg;
    for (; j + 8 <= end; j += 8) {
        int s0 = g1_idx[j],     s1 = g1_idx[j + 1], s2 = g1_idx[j + 2], s3 = g1_idx[j + 3];
        int s4 = g1_idx[j + 4], s5 = g1_idx[j + 5], s6 = g1_idx[j + 6], s7 = g1_idx[j + 7];
        uint2 r0 = g_XH[s0 * 32 + lane];
        uint2 r1 = g_XH[s1 * 32 + lane];
        uint2 r2 = g_XH[s2 * 32 + lane];
        uint2 r3 = g_XH[s3 * 32 + lane];
        uint2 r4 = g_XH[s4 * 32 + lane];
        uint2 r5 = g_XH[s5 * 32 + lane];
        uint2 r6 = g_XH[s6 * 32 + lane];
        uint2 r7 = g_XH[s7 * 32 + lane];
        acc_h(acc, r0); acc_h(acc, r1); acc_h(acc, r2); acc_h(acc, r3);
        acc_h(acc, r4); acc_h(acc, r5); acc_h(acc, r6); acc_h(acc, r7);
    }
    for (; j < end; j++) {
        int s = g1_idx[j];
        acc_h(acc, g_XH[s * 32 + lane]);
    }
    float de = __ldg(degE + e);
    uint2 o;
    o.x = h2_to_u32(__floats2half2_rn(acc.x * de, acc.y * de));
    o.y = h2_to_u32(__floats2half2_rn(acc.z * de, acc.w * de));
    g_XeH[e * 32 + lane] = o;
}

// ---------------------------------------------------------------------------
// SpMM 2 + residual: Xi[v] = (1-a)*degV[v]*sum XeH[s] + a*X0[v]  (warp/node, u8)
// ---------------------------------------------------------------------------
__global__ void spmm2_kernel(const float4* __restrict__ X04,
                             const float* __restrict__ degV,
                             const float* __restrict__ alpha) {
    int v = (blockIdx.x * blockDim.x + threadIdx.x) >> 5;
    if (v >= N_NODES) return;
    int lane = threadIdx.x & 31;
    int beg = g2_off[v], end = g2_off[v + 1];

    float4 acc = make_float4(0.f, 0.f, 0.f, 0.f);
    int j = beg;
    for (; j + 8 <= end; j += 8) {
        int s0 = g2_idx[j],     s1 = g2_idx[j + 1], s2 = g2_idx[j + 2], s3 = g2_idx[j + 3];
        int s4 = g2_idx[j + 4], s5 = g2_idx[j + 5], s6 = g2_idx[j + 6], s7 = g2_idx[j + 7];
        uint2 r0 = g_XeH[s0 * 32 + lane];
        uint2 r1 = g_XeH[s1 * 32 + lane];
        uint2 r2 = g_XeH[s2 * 32 + lane];
        uint2 r3 = g_XeH[s3 * 32 + lane];
        uint2 r4 = g_XeH[s4 * 32 + lane];
        uint2 r5 = g_XeH[s5 * 32 + lane];
        uint2 r6 = g_XeH[s6 * 32 + lane];
        uint2 r7 = g_XeH[s7 * 32 + lane];
        acc_h(acc, r0); acc_h(acc, r1); acc_h(acc, r2); acc_h(acc, r3);
        acc_h(acc, r4); acc_h(acc, r5); acc_h(acc, r6); acc_h(acc, r7);
    }
    for (; j + 4 <= end; j += 4) {
        int s0 = g2_idx[j], s1 = g2_idx[j + 1], s2 = g2_idx[j + 2], s3 = g2_idx[j + 3];
        uint2 r0 = g_XeH[s0 * 32 + lane];
        uint2 r1 = g_XeH[s1 * 32 + lane];
        uint2 r2 = g_XeH[s2 * 32 + lane];
        uint2 r3 = g_XeH[s3 * 32 + lane];
        acc_h(acc, r0); acc_h(acc, r1); acc_h(acc, r2); acc_h(acc, r3);
    }
    for (; j < end; j++) {
        int s = g2_idx[j];
        acc_h(acc, g_XeH[s * 32 + lane]);
    }
    float a = __ldg(alpha);
    float sc = (1.f - a) * __ldg(degV + v);
    float4 x0 = __ldg(X04 + v * 32 + lane);
    float4 xi;
    xi.x = sc * acc.x + a * x0.x;
    xi.y = sc * acc.y + a * x0.y;
    xi.z = sc * acc.z + a * x0.z;
    xi.w = sc * acc.w + a * x0.w;
    reinterpret_cast<float4*>(g_Xv)[v * 32 + lane] = xi;
}

// ---------------------------------------------------------------------------
// GEMM: out = (1-b)*Xi + b*(Xi @ W^T)   (Xi in g_Xv; exact 16-row tiling)
// ---------------------------------------------------------------------------
#define XI_STRIDE 132

__global__ void __launch_bounds__(256, 2)
gemm_kernel(const float* __restrict__ beta, float* __restrict__ out) {
    __shared__ float Xism[16 * XI_STRIDE];

    const int tid = threadIdx.x;
    const int row0 = blockIdx.x * 16;
    const float bb = __ldg(beta);
    const float omb = 1.f - bb;

    const int warp = tid >> 5, lane = tid & 31;
    const int gid = lane >> 2, tig = lane & 3;
    const int nt0 = warp, nt1 = warp + 8;

    float2 bf0[16], bf1[16];
#pragma unroll
    for (int kk = 0; kk < 16; kk++) {
        bf0[kk] = __ldg(&g_Wp[(kk * 4 + tig) * 128 + nt0 * 8 + gid]);
        bf1[kk] = __ldg(&g_Wp[(kk * 4 + tig) * 128 + nt1 * 8 + gid]);
    }

    const float4* Xv4 = reinterpret_cast<const float4*>(g_Xv);
#pragma unroll
    for (int i = tid; i < 16 * 32; i += 256) {
        int r = i >> 5, c4 = i & 31;
        float4 xi = Xv4[(row0 + r) * 32 + c4];
        *reinterpret_cast<float4*>(&Xism[r * XI_STRIDE + c4 * 4]) = xi;
    }
    __syncthreads();

    float c00 = 0.f, c01 = 0.f, c02 = 0.f, c03 = 0.f;
    float c10 = 0.f, c11 = 0.f, c12 = 0.f, c13 = 0.f;

#pragma unroll
    for (int kk = 0; kk < 16; kk++) {
        int c = kk * 8 + tig;
        uint32_t a0 = f2tf32(Xism[gid * XI_STRIDE + c]);
        uint32_t a1 = f2tf32(Xism[(gid + 8) * XI_STRIDE + c]);
        uint32_t a2 = f2tf32(Xism[gid * XI_STRIDE + c + 4]);
        uint32_t a3 = f2tf32(Xism[(gid + 8) * XI_STRIDE + c + 4]);
        uint32_t b00 = __float_as_uint(bf0[kk].x);
        uint32_t b01 = __float_as_uint(bf0[kk].y);
        uint32_t b10 = __float_as_uint(bf1[kk].x);
        uint32_t b11 = __float_as_uint(bf1[kk].y);
        asm volatile(
            "mma.sync.aligned.m16n8k8.row.col.f32.tf32.tf32.f32 "
            "{%0,%1,%2,%3}, {%4,%5,%6,%7}, {%8,%9}, {%0,%1,%2,%3};"
            : "+f"(c00), "+f"(c01), "+f"(c02), "+f"(c03)
            : "r"(a0), "r"(a1), "r"(a2), "r"(a3), "r"(b00), "r"(b01));
        asm volatile(
            "mma.sync.aligned.m16n8k8.row.col.f32.tf32.tf32.f32 "
            "{%0,%1,%2,%3}, {%4,%5,%6,%7}, {%8,%9}, {%0,%1,%2,%3};"
            : "+f"(c10), "+f"(c11), "+f"(c12), "+f"(c13)
            : "r"(a0), "r"(a1), "r"(a2), "r"(a3), "r"(b10), "r"(b11));
    }

    const int r0 = row0 + gid;
    const int r1 = r0 + 8;
    {
        int col = nt0 * 8 + 2 * tig;
        float xi0 = Xism[gid * XI_STRIDE + col];
        float xi1 = Xism[gid * XI_STRIDE + col + 1];
        *reinterpret_cast<float2*>(out + (long)r0 * 128 + col) =
            make_float2(omb * xi0 + bb * c00, omb * xi1 + bb * c01);
        xi0 = Xism[(gid + 8) * XI_STRIDE + col];
        xi1 = Xism[(gid + 8) * XI_STRIDE + col + 1];
        *reinterpret_cast<float2*>(out + (long)r1 * 128 + col) =
            make_float2(omb * xi0 + bb * c02, omb * xi1 + bb * c03);

        col = nt1 * 8 + 2 * tig;
        xi0 = Xism[gid * XI_STRIDE + col];
        xi1 = Xism[gid * XI_STRIDE + col + 1];
        *reinterpret_cast<float2*>(out + (long)r0 * 128 + col) =
            make_float2(omb * xi0 + bb * c10, omb * xi1 + bb * c11);
        xi0 = Xism[(gid + 8) * XI_STRIDE + col];
        xi1 = Xism[(gid + 8) * XI_STRIDE + col + 1];
        *reinterpret_cast<float2*>(out + (long)r1 * 128 + col) =
            make_float2(omb * xi0 + bb * c12, omb * xi1 + bb * c13);
    }
}

// ---------------------------------------------------------------------------
// kernel_launch
// ---------------------------------------------------------------------------
extern "C" void kernel_launch(void* const* d_in, const int* in_sizes, int n_in,
                              void* d_out, int out_size) {
    const float* X     = (const float*)d_in[0];
    const float* X0    = (const float*)d_in[1];
    const float* degE  = (const float*)d_in[2];
    const float* degV  = (const float*)d_in[3];
    const float* alpha = (const float*)d_in[4];
    const float* beta  = (const float*)d_in[5];
    const float* W     = (const float*)d_in[6];
    const int*   g1s   = (const int*)d_in[7];
    const int*   g1d   = (const int*)d_in[8];
    const int*   g2s   = (const int*)d_in[9];
    const int*   g2d   = (const int*)d_in[10];
    float* out = (float*)d_out;

    // X->fp16 + zero counters + W prep (merged)
    prep_kernel<<<CONV_BLKS + ZERO_BLKS + WPREP_BLKS, 256>>>((const float4*)X, W);

    // CSR build for both graphs
    hist_kernel<<<(NNZ / 4 + 255) / 256, 256>>>((const int4*)g1d, (const int4*)g2d);
    scanA_kernel<<<NBT, SCAN_TPB>>>();
    scanC_kernel<<<NBT, SCAN_TPB>>>();
    fill_kernel<<<(NNZ / 2 + 255) / 256, 256>>>((const int2*)g1s, (const int2*)g1d,
                                                (const int2*)g2s, (const int2*)g2d);

    // Gather-sum SpMMs (fp16 operands, fp32 accumulate)
    spmm1_kernel<<<(N_EDGES * 32 + 255) / 256, 256>>>(degE);
    spmm2_kernel<<<(N_NODES * 32 + 255) / 256, 256>>>((const float4*)X0, degV, alpha);

    // tf32 GEMM + residual epilogue (100000 = 6250 * 16 exact)
    gemm_kernel<<<N_NODES / 16, 256>>>(beta, out);
}

// round 11
// speedup vs baseline: 1.0159x; 1.0159x over previous
#include <cuda_runtime.h>
#include <cuda_fp16.h>
#include <cstdint>

#define N_NODES 100000
#define N_EDGES 20000
#define NNZ     800000
#define D       128

// Scan tiling
#define SCAN_TPB   256
#define SCAN_PER   8
#define SCAN_CHUNK (SCAN_TPB * SCAN_PER)                      // 2048
#define NB1 ((N_EDGES + SCAN_CHUNK - 1) / SCAN_CHUNK)         // 10
#define NB2 ((N_NODES + SCAN_CHUNK - 1) / SCAN_CHUNK)         // 49
#define NBT (NB1 + NB2)                                       // 59

// ---------------------------------------------------------------------------
// Device-global scratch (allocation-free rule)
// ---------------------------------------------------------------------------
__device__ __align__(16) uint2 g_XeH[N_EDGES * 32]; // Xe fp16 (2x half2/lane), 5.12 MB
__device__ __align__(16) uint2 g_XiH[N_NODES * 32]; // Xi fp16, 25.6 MB
__device__ __align__(16) float2 g_Wp[64 * 128];     // packed tf32 B fragments, 64 KB

__device__ int g1_cnt[N_EDGES];
__device__ int g1_off[N_EDGES + 1];
__device__ int g1_cur[N_EDGES];
__device__ int g1_idx[NNZ];
__device__ int g2_cnt[N_NODES];
__device__ int g2_off[N_NODES + 1];
__device__ int g2_cur[N_NODES];
__device__ int g2_idx[NNZ];

__device__ int g_thr_excl[NBT * SCAN_TPB];
__device__ int g_blk_sum[NBT];

// ---------------------------------------------------------------------------
// helpers
// ---------------------------------------------------------------------------
__device__ __forceinline__ uint32_t h2_to_u32(__half2 h) {
    return *reinterpret_cast<uint32_t*>(&h);
}
__device__ __forceinline__ __half2 u32_to_h2(uint32_t u) {
    return *reinterpret_cast<__half2*>(&u);
}
__device__ __forceinline__ uint32_t f2tf32(float f) {
    uint32_t r;
    asm("cvt.rna.tf32.f32 %0, %1;" : "=r"(r) : "f"(f));
    return r;
}
__device__ __forceinline__ void acc_h(float4& acc, uint2 r) {
    float2 f0 = __half22float2(u32_to_h2(r.x));
    float2 f1 = __half22float2(u32_to_h2(r.y));
    acc.x += f0.x; acc.y += f0.y; acc.z += f1.x; acc.w += f1.y;
}

// ---------------------------------------------------------------------------
// Merged: zero counters (blocks 0..390) + W prep (blocks 391..422)
// ---------------------------------------------------------------------------
#define ZERO_BLKS ((N_NODES + 255) / 256)        // 391
#define WPREP_BLKS 32

__global__ void zero_wprep_kernel(const float* __restrict__ W) {
    if (blockIdx.x < ZERO_BLKS) {
        int i = blockIdx.x * blockDim.x + threadIdx.x;
        if (i < N_EDGES) g1_cnt[i] = 0;
        if (i < N_NODES) g2_cnt[i] = 0;
    } else {
        int p = (blockIdx.x - ZERO_BLKS) * blockDim.x + threadIdx.x;  // 8192 total
        if (p < 64 * 128) {
            int n = p & 127;
            int tig = (p >> 7) & 3;
            int kk = p >> 9;
            float w0 = __ldg(W + n * 128 + kk * 8 + tig);
            float w1 = __ldg(W + n * 128 + kk * 8 + tig + 4);
            float2 o;
            o.x = __uint_as_float(f2tf32(w0));
            o.y = __uint_as_float(f2tf32(w1));
            g_Wp[p] = o;
        }
    }
}

// ---------------------------------------------------------------------------
// Histogram, both graphs (int4-vectorized)
// ---------------------------------------------------------------------------
__global__ void hist_kernel(const int4* __restrict__ g1d4,
                            const int4* __restrict__ g2d4) {
    int i = blockIdx.x * blockDim.x + threadIdx.x;
    if (i >= NNZ / 4) return;
    int4 d1 = __ldg(g1d4 + i);
    atomicAdd(&g1_cnt[d1.x], 1);
    atomicAdd(&g1_cnt[d1.y], 1);
    atomicAdd(&g1_cnt[d1.z], 1);
    atomicAdd(&g1_cnt[d1.w], 1);
    int4 d2 = __ldg(g2d4 + i);
    atomicAdd(&g2_cnt[d2.x], 1);
    atomicAdd(&g2_cnt[d2.y], 1);
    atomicAdd(&g2_cnt[d2.z], 1);
    atomicAdd(&g2_cnt[d2.w], 1);
}

// Phase A: per-block partial scan.
__global__ void scanA_kernel() {
    const int bid = blockIdx.x;
    const int t = threadIdx.x;
    const int* cnt; int n, lbase;
    if (bid < NB1) { cnt = g1_cnt; n = N_EDGES; lbase = bid * SCAN_CHUNK; }
    else           { cnt = g2_cnt; n = N_NODES; lbase = (bid - NB1) * SCAN_CHUNK; }

    int s = 0;
    const int i0 = lbase + t * SCAN_PER;
#pragma unroll
    for (int k = 0; k < SCAN_PER; k++) {
        int i = i0 + k;
        s += (i < n) ? cnt[i] : 0;
    }

    const int lane = t & 31, wid = t >> 5;
    int v = s;
#pragma unroll
    for (int o = 1; o < 32; o <<= 1) {
        int u = __shfl_up_sync(0xffffffffu, v, o);
        if (lane >= o) v += u;
    }
    __shared__ int ws[8];
    if (lane == 31) ws[wid] = v;
    __syncthreads();
    if (t < 8) {
        int w = ws[t];
#pragma unroll
        for (int o = 1; o < 8; o <<= 1) {
            int u = __shfl_up_sync(0xffu, w, o);
            if (t >= o) w += u;
        }
        ws[t] = w;
    }
    __syncthreads();

    int excl = v - s + (wid ? ws[wid - 1] : 0);
    g_thr_excl[bid * SCAN_TPB + t] = excl;
    if (t == SCAN_TPB - 1) g_blk_sum[bid] = excl + s;
}

// Phase C (fused B).
__global__ void scanC_kernel() {
    __shared__ int be[NBT];
    __shared__ int wtot;
    const int bid = blockIdx.x;
    const int t = threadIdx.x;

    if (t < 64) {
        int v = (t < NBT) ? g_blk_sum[t] : 0;
        const int lane = t & 31;
        int s = v;
#pragma unroll
        for (int o = 1; o < 32; o <<= 1) {
            int u = __shfl_up_sync(0xffffffffu, s, o);
            if (lane >= o) s += u;
        }
        if (t == 31) wtot = s;
        if (t < NBT) be[t] = s - v;
    }
    __syncthreads();
    if (t >= 32 && t < 64 && t < NBT) be[t] += wtot;
    __syncthreads();
    if (t < NBT && t >= NB1) be[t] -= NNZ;
    __syncthreads();

    const int* cnt; int* off; int* cur; int n, lbase;
    if (bid < NB1) { cnt = g1_cnt; off = g1_off; cur = g1_cur; n = N_EDGES; lbase = bid * SCAN_CHUNK; }
    else           { cnt = g2_cnt; off = g2_off; cur = g2_cur; n = N_NODES; lbase = (bid - NB1) * SCAN_CHUNK; }

    int base = be[bid] + g_thr_excl[bid * SCAN_TPB + t];
    const int i0 = lbase + t * SCAN_PER;
#pragma unroll
    for (int k = 0; k < SCAN_PER; k++) {
        int i = i0 + k;
        if (i < n) {
            off[i] = base;
            cur[i] = base;
            base += cnt[i];
        }
    }
    if (bid == 0 && t == 0) {
        g1_off[N_EDGES] = NNZ;
        g2_off[N_NODES] = NNZ;
    }
}

// Fill, both graphs (int2-vectorized)
__global__ void fill_kernel(const int2* __restrict__ g1s2, const int2* __restrict__ g1d2,
                            const int2* __restrict__ g2s2, const int2* __restrict__ g2d2) {
    int i = blockIdx.x * blockDim.x + threadIdx.x;
    if (i >= NNZ / 2) return;
    int2 s1 = __ldg(g1s2 + i);
    int2 d1 = __ldg(g1d2 + i);
    int p0 = atomicAdd(&g1_cur[d1.x], 1);
    g1_idx[p0] = s1.x;
    int p1 = atomicAdd(&g1_cur[d1.y], 1);
    g1_idx[p1] = s1.y;
    int2 s2 = __ldg(g2s2 + i);
    int2 d2 = __ldg(g2d2 + i);
    int q0 = atomicAdd(&g2_cur[d2.x], 1);
    g2_idx[q0] = s2.x;
    int q1 = atomicAdd(&g2_cur[d2.y], 1);
    g2_idx[q1] = s2.y;
}

// ---------------------------------------------------------------------------
// SpMM 1: XeH[e] = fp16( degE[e] * sum X[s] )   (warp/edge, fp32 gather, u8)
// ---------------------------------------------------------------------------
__global__ void spmm1_kernel(const float4* __restrict__ X4,
                             const float* __restrict__ degE) {
    int e = (blockIdx.x * blockDim.x + threadIdx.x) >> 5;
    if (e >= N_EDGES) return;
    int lane = threadIdx.x & 31;
    int beg = g1_off[e], end = g1_off[e + 1];

    float4 acc = make_float4(0.f, 0.f, 0.f, 0.f);
    int j = beg;
    for (; j + 8 <= end; j += 8) {
        int s0 = g1_idx[j],     s1 = g1_idx[j + 1], s2 = g1_idx[j + 2], s3 = g1_idx[j + 3];
        int s4 = g1_idx[j + 4], s5 = g1_idx[j + 5], s6 = g1_idx[j + 6], s7 = g1_idx[j + 7];
        float4 v0 = __ldg(X4 + s0 * 32 + lane);
        float4 v1 = __ldg(X4 + s1 * 32 + lane);
        float4 v2 = __ldg(X4 + s2 * 32 + lane);
        float4 v3 = __ldg(X4 + s3 * 32 + lane);
        float4 v4 = __ldg(X4 + s4 * 32 + lane);
        float4 v5 = __ldg(X4 + s5 * 32 + lane);
        float4 v6 = __ldg(X4 + s6 * 32 + lane);
        float4 v7 = __ldg(X4 + s7 * 32 + lane);
        acc.x += ((v0.x + v1.x) + (v2.x + v3.x)) + ((v4.x + v5.x) + (v6.x + v7.x));
        acc.y += ((v0.y + v1.y) + (v2.y + v3.y)) + ((v4.y + v5.y) + (v6.y + v7.y));
        acc.z += ((v0.z + v1.z) + (v2.z + v3.z)) + ((v4.z + v5.z) + (v6.z + v7.z));
        acc.w += ((v0.w + v1.w) + (v2.w + v3.w)) + ((v4.w + v5.w) + (v6.w + v7.w));
    }
    for (; j < end; j++) {
        int s = g1_idx[j];
        float4 v = __ldg(X4 + s * 32 + lane);
        acc.x += v.x; acc.y += v.y; acc.z += v.z; acc.w += v.w;
    }
    float de = __ldg(degE + e);
    uint2 o;
    o.x = h2_to_u32(__floats2half2_rn(acc.x * de, acc.y * de));
    o.y = h2_to_u32(__floats2half2_rn(acc.z * de, acc.w * de));
    g_XeH[e * 32 + lane] = o;
}

// ---------------------------------------------------------------------------
// SpMM 2 + residual: XiH[v] = fp16( (1-a)*degV[v]*sum XeH[s] + a*X0[v] )
// fp16 gather, fp32 accumulate, fp16 Xi output              (warp per node)
// ---------------------------------------------------------------------------
__global__ void spmm2_kernel(const float4* __restrict__ X04,
                             const float* __restrict__ degV,
                             const float* __restrict__ alpha) {
    int v = (blockIdx.x * blockDim.x + threadIdx.x) >> 5;
    if (v >= N_NODES) return;
    int lane = threadIdx.x & 31;
    int beg = g2_off[v], end = g2_off[v + 1];

    float4 acc = make_float4(0.f, 0.f, 0.f, 0.f);
    int j = beg;
    for (; j + 8 <= end; j += 8) {
        int s0 = g2_idx[j],     s1 = g2_idx[j + 1], s2 = g2_idx[j + 2], s3 = g2_idx[j + 3];
        int s4 = g2_idx[j + 4], s5 = g2_idx[j + 5], s6 = g2_idx[j + 6], s7 = g2_idx[j + 7];
        uint2 r0 = g_XeH[s0 * 32 + lane];
        uint2 r1 = g_XeH[s1 * 32 + lane];
        uint2 r2 = g_XeH[s2 * 32 + lane];
        uint2 r3 = g_XeH[s3 * 32 + lane];
        uint2 r4 = g_XeH[s4 * 32 + lane];
        uint2 r5 = g_XeH[s5 * 32 + lane];
        uint2 r6 = g_XeH[s6 * 32 + lane];
        uint2 r7 = g_XeH[s7 * 32 + lane];
        acc_h(acc, r0); acc_h(acc, r1); acc_h(acc, r2); acc_h(acc, r3);
        acc_h(acc, r4); acc_h(acc, r5); acc_h(acc, r6); acc_h(acc, r7);
    }
    for (; j + 4 <= end; j += 4) {
        int s0 = g2_idx[j], s1 = g2_idx[j + 1], s2 = g2_idx[j + 2], s3 = g2_idx[j + 3];
        uint2 r0 = g_XeH[s0 * 32 + lane];
        uint2 r1 = g_XeH[s1 * 32 + lane];
        uint2 r2 = g_XeH[s2 * 32 + lane];
        uint2 r3 = g_XeH[s3 * 32 + lane];
        acc_h(acc, r0); acc_h(acc, r1); acc_h(acc, r2); acc_h(acc, r3);
    }
    for (; j < end; j++) {
        int s = g2_idx[j];
        acc_h(acc, g_XeH[s * 32 + lane]);
    }
    float a = __ldg(alpha);
    float sc = (1.f - a) * __ldg(degV + v);
    float4 x0 = __ldg(X04 + v * 32 + lane);
    float xi0 = sc * acc.x + a * x0.x;
    float xi1 = sc * acc.y + a * x0.y;
    float xi2 = sc * acc.z + a * x0.z;
    float xi3 = sc * acc.w + a * x0.w;
    uint2 o;
    o.x = h2_to_u32(__floats2half2_rn(xi0, xi1));
    o.y = h2_to_u32(__floats2half2_rn(xi2, xi3));
    g_XiH[v * 32 + lane] = o;
}

// ---------------------------------------------------------------------------
// GEMM: out = (1-b)*Xi + b*(Xi @ W^T)   (Xi fp16 in g_XiH; exact 16-row tiling)
// Tile staged into smem as fp32 (widened on load) — mma path unchanged.
// ---------------------------------------------------------------------------
#define XI_STRIDE 132

__global__ void __launch_bounds__(256, 2)
gemm_kernel(const float* __restrict__ beta, float* __restrict__ out) {
    __shared__ float Xism[16 * XI_STRIDE];

    const int tid = threadIdx.x;
    const int row0 = blockIdx.x * 16;
    const float bb = __ldg(beta);
    const float omb = 1.f - bb;

    const int warp = tid >> 5, lane = tid & 31;
    const int gid = lane >> 2, tig = lane & 3;
    const int nt0 = warp, nt1 = warp + 8;

    float2 bf0[16], bf1[16];
#pragma unroll
    for (int kk = 0; kk < 16; kk++) {
        bf0[kk] = __ldg(&g_Wp[(kk * 4 + tig) * 128 + nt0 * 8 + gid]);
        bf1[kk] = __ldg(&g_Wp[(kk * 4 + tig) * 128 + nt1 * 8 + gid]);
    }

    // Stage Xi tile: fp16 global -> fp32 smem (16 rows x 32 uint2 slots)
#pragma unroll
    for (int i = tid; i < 16 * 32; i += 256) {
        int r = i >> 5, c4 = i & 31;
        uint2 h = g_XiH[(row0 + r) * 32 + c4];
        float2 f0 = __half22float2(u32_to_h2(h.x));
        float2 f1 = __half22float2(u32_to_h2(h.y));
        float4 xi = make_float4(f0.x, f0.y, f1.x, f1.y);
        *reinterpret_cast<float4*>(&Xism[r * XI_STRIDE + c4 * 4]) = xi;
    }
    __syncthreads();

    float c00 = 0.f, c01 = 0.f, c02 = 0.f, c03 = 0.f;
    float c10 = 0.f, c11 = 0.f, c12 = 0.f, c13 = 0.f;

#pragma unroll
    for (int kk = 0; kk < 16; kk++) {
        int c = kk * 8 + tig;
        uint32_t a0 = f2tf32(Xism[gid * XI_STRIDE + c]);
        uint32_t a1 = f2tf32(Xism[(gid + 8) * XI_STRIDE + c]);
        uint32_t a2 = f2tf32(Xism[gid * XI_STRIDE + c + 4]);
        uint32_t a3 = f2tf32(Xism[(gid + 8) * XI_STRIDE + c + 4]);
        uint32_t b00 = __float_as_uint(bf0[kk].x);
        uint32_t b01 = __float_as_uint(bf0[kk].y);
        uint32_t b10 = __float_as_uint(bf1[kk].x);
        uint32_t b11 = __float_as_uint(bf1[kk].y);
        asm volatile(
            "mma.sync.aligned.m16n8k8.row.col.f32.tf32.tf32.f32 "
            "{%0,%1,%2,%3}, {%4,%5,%6,%7}, {%8,%9}, {%0,%1,%2,%3};"
            : "+f"(c00), "+f"(c01), "+f"(c02), "+f"(c03)
            : "r"(a0), "r"(a1), "r"(a2), "r"(a3), "r"(b00), "r"(b01));
        asm volatile(
            "mma.sync.aligned.m16n8k8.row.col.f32.tf32.tf32.f32 "
            "{%0,%1,%2,%3}, {%4,%5,%6,%7}, {%8,%9}, {%0,%1,%2,%3};"
            : "+f"(c10), "+f"(c11), "+f"(c12), "+f"(c13)
            : "r"(a0), "r"(a1), "r"(a2), "r"(a3), "r"(b10), "r"(b11));
    }

    const int r0 = row0 + gid;
    const int r1 = r0 + 8;
    {
        int col = nt0 * 8 + 2 * tig;
        float xi0 = Xism[gid * XI_STRIDE + col];
        float xi1 = Xism[gid * XI_STRIDE + col + 1];
        *reinterpret_cast<float2*>(out + (long)r0 * 128 + col) =
            make_float2(omb * xi0 + bb * c00, omb * xi1 + bb * c01);
        xi0 = Xism[(gid + 8) * XI_STRIDE + col];
        xi1 = Xism[(gid + 8) * XI_STRIDE + col + 1];
        *reinterpret_cast<float2*>(out + (long)r1 * 128 + col) =
            make_float2(omb * xi0 + bb * c02, omb * xi1 + bb * c03);

        col = nt1 * 8 + 2 * tig;
        xi0 = Xism[gid * XI_STRIDE + col];
        xi1 = Xism[gid * XI_STRIDE + col + 1];
        *reinterpret_cast<float2*>(out + (long)r0 * 128 + col) =
            make_float2(omb * xi0 + bb * c10, omb * xi1 + bb * c11);
        xi0 = Xism[(gid + 8) * XI_STRIDE + col];
        xi1 = Xism[(gid + 8) * XI_STRIDE + col + 1];
        *reinterpret_cast<float2*>(out + (long)r1 * 128 + col) =
            make_float2(omb * xi0 + bb * c12, omb * xi1 + bb * c13);
    }
}

// ---------------------------------------------------------------------------
// kernel_launch
// ---------------------------------------------------------------------------
extern "C" void kernel_launch(void* const* d_in, const int* in_sizes, int n_in,
                              void* d_out, int out_size) {
    const float* X     = (const float*)d_in[0];
    const float* X0    = (const float*)d_in[1];
    const float* degE  = (const float*)d_in[2];
    const float* degV  = (const float*)d_in[3];
    const float* alpha = (const float*)d_in[4];
    const float* beta  = (const float*)d_in[5];
    const float* W     = (const float*)d_in[6];
    const int*   g1s   = (const int*)d_in[7];
    const int*   g1d   = (const int*)d_in[8];
    const int*   g2s   = (const int*)d_in[9];
    const int*   g2d   = (const int*)d_in[10];
    float* out = (float*)d_out;

    // zero counters + W prep (merged; no X conversion — reverted, was neutral)
    zero_wprep_kernel<<<ZERO_BLKS + WPREP_BLKS, 256>>>(W);

    // CSR build for both graphs
    hist_kernel<<<(NNZ / 4 + 255) / 256, 256>>>((const int4*)g1d, (const int4*)g2d);
    scanA_kernel<<<NBT, SCAN_TPB>>>();
    scanC_kernel<<<NBT, SCAN_TPB>>>();
    fill_kernel<<<(NNZ / 2 + 255) / 256, 256>>>((const int2*)g1s, (const int2*)g1d,
                                                (const int2*)g2s, (const int2*)g2d);

    // Gather-sum SpMMs (fp32 X gather; fp16 Xe and Xi intermediates)
    spmm1_kernel<<<(N_EDGES * 32 + 255) / 256, 256>>>((const float4*)X, degE);
    spmm2_kernel<<<(N_NODES * 32 + 255) / 256, 256>>>((const float4*)X0, degV, alpha);

    // tf32 GEMM + residual epilogue (100000 = 6250 * 16 exact)
    gemm_kernel<<<N_NODES / 16, 256>>>(beta, out);
}

// round 12
// speedup vs baseline: 1.0205x; 1.0046x over previous
#include <cuda_runtime.h>
#include <cuda_fp16.h>
#include <cstdint>

#define N_NODES 100000
#define N_EDGES 20000
#define NNZ     800000
#define D       128

// Scan tiling
#define SCAN_TPB   256
#define SCAN_PER   8
#define SCAN_CHUNK (SCAN_TPB * SCAN_PER)                      // 2048
#define NB1 ((N_EDGES + SCAN_CHUNK - 1) / SCAN_CHUNK)         // 10
#define NB2 ((N_NODES + SCAN_CHUNK - 1) / SCAN_CHUNK)         // 49
#define NBT (NB1 + NB2)                                       // 59

// ---------------------------------------------------------------------------
// Device-global scratch (allocation-free rule)
// ---------------------------------------------------------------------------
__device__ __align__(16) uint2 g_XeH[N_EDGES * 32]; // Xe fp16 (2x half2/lane), 5.12 MB
__device__ __align__(16) uint2 g_XiH[N_NODES * 32]; // Xi fp16, 25.6 MB
__device__ __align__(16) float2 g_Wp[64 * 128];     // packed tf32 B fragments, 64 KB

__device__ int g1_cnt[N_EDGES];
__device__ int g1_off[N_EDGES + 1];
__device__ int g1_cur[N_EDGES];
__device__ int g1_idx[NNZ];
__device__ int g2_cnt[N_NODES];
__device__ int g2_off[N_NODES + 1];
__device__ int g2_cur[N_NODES];
__device__ int g2_idx[NNZ];

__device__ int g_blk_sum[NBT];
__device__ int g_ready;            // reset by prep each replay

// ---------------------------------------------------------------------------
// helpers
// ---------------------------------------------------------------------------
__device__ __forceinline__ uint32_t h2_to_u32(__half2 h) {
    return *reinterpret_cast<uint32_t*>(&h);
}
__device__ __forceinline__ __half2 u32_to_h2(uint32_t u) {
    return *reinterpret_cast<__half2*>(&u);
}
__device__ __forceinline__ uint32_t f2tf32(float f) {
    uint32_t r;
    asm("cvt.rna.tf32.f32 %0, %1;" : "=r"(r) : "f"(f));
    return r;
}
__device__ __forceinline__ void acc_h(float4& acc, uint2 r) {
    float2 f0 = __half22float2(u32_to_h2(r.x));
    float2 f1 = __half22float2(u32_to_h2(r.y));
    acc.x += f0.x; acc.y += f0.y; acc.z += f1.x; acc.w += f1.y;
}

// ---------------------------------------------------------------------------
// Prep: zero counters + ready flag (blocks 0..390) + W prep (391..422)
// ---------------------------------------------------------------------------
#define ZERO_BLKS ((N_NODES + 255) / 256)        // 391
#define WPREP_BLKS 32

__global__ void prep_kernel(const float* __restrict__ W) {
    if (blockIdx.x < ZERO_BLKS) {
        int i = blockIdx.x * blockDim.x + threadIdx.x;
        if (i < N_EDGES) g1_cnt[i] = 0;
        if (i < N_NODES) g2_cnt[i] = 0;
        if (i == 0) g_ready = 0;
    } else {
        int p = (blockIdx.x - ZERO_BLKS) * blockDim.x + threadIdx.x;  // 8192 total
        if (p < 64 * 128) {
            int n = p & 127;
            int tig = (p >> 7) & 3;
            int kk = p >> 9;
            float w0 = __ldg(W + n * 128 + kk * 8 + tig);
            float w1 = __ldg(W + n * 128 + kk * 8 + tig + 4);
            float2 o;
            o.x = __uint_as_float(f2tf32(w0));
            o.y = __uint_as_float(f2tf32(w1));
            g_Wp[p] = o;
        }
    }
}

// ---------------------------------------------------------------------------
// Histogram, both graphs (int4-vectorized)
// ---------------------------------------------------------------------------
__global__ void hist_kernel(const int4* __restrict__ g1d4,
                            const int4* __restrict__ g2d4) {
    int i = blockIdx.x * blockDim.x + threadIdx.x;
    if (i >= NNZ / 4) return;
    int4 d1 = __ldg(g1d4 + i);
    atomicAdd(&g1_cnt[d1.x], 1);
    atomicAdd(&g1_cnt[d1.y], 1);
    atomicAdd(&g1_cnt[d1.z], 1);
    atomicAdd(&g1_cnt[d1.w], 1);
    int4 d2 = __ldg(g2d4 + i);
    atomicAdd(&g2_cnt[d2.x], 1);
    atomicAdd(&g2_cnt[d2.y], 1);
    atomicAdd(&g2_cnt[d2.z], 1);
    atomicAdd(&g2_cnt[d2.w], 1);
}

// ---------------------------------------------------------------------------
// Fused scan: single launch, 59 blocks (all co-resident; 59 < 148 SMs).
// Phase 1: per-block sums -> publish. Phase 2: spin on ready counter.
// Phase 3: every block scans the 59 sums redundantly, writes off/cur from
// register-held counts.
// ---------------------------------------------------------------------------
__global__ void scan_fused_kernel() {
    const int bid = blockIdx.x;
    const int t = threadIdx.x;
    const int* cnt; int* off; int* cur; int n, lbase;
    if (bid < NB1) { cnt = g1_cnt; off = g1_off; cur = g1_cur; n = N_EDGES; lbase = bid * SCAN_CHUNK; }
    else           { cnt = g2_cnt; off = g2_off; cur = g2_cur; n = N_NODES; lbase = (bid - NB1) * SCAN_CHUNK; }

    // Phase 1: load 8 counters into registers, per-thread sum, block scan
    int c[SCAN_PER];
    int s = 0;
    const int i0 = lbase + t * SCAN_PER;
#pragma unroll
    for (int k = 0; k < SCAN_PER; k++) {
        int i = i0 + k;
        c[k] = (i < n) ? cnt[i] : 0;
        s += c[k];
    }

    const int lane = t & 31, wid = t >> 5;
    int v = s;
#pragma unroll
    for (int o = 1; o < 32; o <<= 1) {
        int u = __shfl_up_sync(0xffffffffu, v, o);
        if (lane >= o) v += u;
    }
    __shared__ int ws[8];
    if (lane == 31) ws[wid] = v;
    __syncthreads();
    if (t < 8) {
        int w = ws[t];
#pragma unroll
        for (int o = 1; o < 8; o <<= 1) {
            int u = __shfl_up_sync(0xffu, w, o);
            if (t >= o) w += u;
        }
        ws[t] = w;
    }
    __syncthreads();

    int excl = v - s + (wid ? ws[wid - 1] : 0);     // per-thread exclusive base
    // Publish block total (thread 255 holds excl+s == block total)
    if (t == SCAN_TPB - 1) {
        g_blk_sum[bid] = excl + s;
        __threadfence();
        atomicAdd(&g_ready, 1);
    }

    // Phase 2: wait for all 59 block sums
    if (t == 0) {
        volatile int* rdy = &g_ready;
        while (*rdy < NBT) { }
    }
    __syncthreads();
    __threadfence();   // acquire ordering for g_blk_sum reads

    // Phase 3: scan the 59 sums (threads 0..63), get this block's base
    __shared__ int be[64];
    __shared__ int wtot;
    if (t < 64) {
        int bv = (t < NBT) ? g_blk_sum[t] : 0;
        int bs = bv;
#pragma unroll
        for (int o = 1; o < 32; o <<= 1) {
            int u = __shfl_up_sync(0xffffffffu, bs, o);
            if ((t & 31) >= o) bs += u;
        }
        if (t == 31) wtot = bs;
        be[t] = bs - bv;
    }
    __syncthreads();
    if (t >= 32 && t < 64) be[t] += wtot;
    __syncthreads();

    int base = be[bid] + excl;
    if (bid >= NB1) base -= NNZ;                   // g2 segment rebase
#pragma unroll
    for (int k = 0; k < SCAN_PER; k++) {
        int i = i0 + k;
        if (i < n) {
            off[i] = base;
            cur[i] = base;
            base += c[k];
        }
    }
    if (bid == 0 && t == 0) {
        g1_off[N_EDGES] = NNZ;
        g2_off[N_NODES] = NNZ;
    }
}

// Fill, both graphs (int2-vectorized)
__global__ void fill_kernel(const int2* __restrict__ g1s2, const int2* __restrict__ g1d2,
                            const int2* __restrict__ g2s2, const int2* __restrict__ g2d2) {
    int i = blockIdx.x * blockDim.x + threadIdx.x;
    if (i >= NNZ / 2) return;
    int2 s1 = __ldg(g1s2 + i);
    int2 d1 = __ldg(g1d2 + i);
    int p0 = atomicAdd(&g1_cur[d1.x], 1);
    g1_idx[p0] = s1.x;
    int p1 = atomicAdd(&g1_cur[d1.y], 1);
    g1_idx[p1] = s1.y;
    int2 s2 = __ldg(g2s2 + i);
    int2 d2 = __ldg(g2d2 + i);
    int q0 = atomicAdd(&g2_cur[d2.x], 1);
    g2_idx[q0] = s2.x;
    int q1 = atomicAdd(&g2_cur[d2.y], 1);
    g2_idx[q1] = s2.y;
}

// ---------------------------------------------------------------------------
// SpMM 1: XeH[e] = fp16( degE[e] * sum X[s] )   (warp/edge, fp32 gather, u8)
// ---------------------------------------------------------------------------
__global__ void spmm1_kernel(const float4* __restrict__ X4,
                             const float* __restrict__ degE) {
    int e = (blockIdx.x * blockDim.x + threadIdx.x) >> 5;
    if (e >= N_EDGES) return;
    int lane = threadIdx.x & 31;
    int beg = g1_off[e], end = g1_off[e + 1];

    float4 acc = make_float4(0.f, 0.f, 0.f, 0.f);
    int j = beg;
    for (; j + 8 <= end; j += 8) {
        int s0 = g1_idx[j],     s1 = g1_idx[j + 1], s2 = g1_idx[j + 2], s3 = g1_idx[j + 3];
        int s4 = g1_idx[j + 4], s5 = g1_idx[j + 5], s6 = g1_idx[j + 6], s7 = g1_idx[j + 7];
        float4 v0 = __ldg(X4 + s0 * 32 + lane);
        float4 v1 = __ldg(X4 + s1 * 32 + lane);
        float4 v2 = __ldg(X4 + s2 * 32 + lane);
        float4 v3 = __ldg(X4 + s3 * 32 + lane);
        float4 v4 = __ldg(X4 + s4 * 32 + lane);
        float4 v5 = __ldg(X4 + s5 * 32 + lane);
        float4 v6 = __ldg(X4 + s6 * 32 + lane);
        float4 v7 = __ldg(X4 + s7 * 32 + lane);
        acc.x += ((v0.x + v1.x) + (v2.x + v3.x)) + ((v4.x + v5.x) + (v6.x + v7.x));
        acc.y += ((v0.y + v1.y) + (v2.y + v3.y)) + ((v4.y + v5.y) + (v6.y + v7.y));
        acc.z += ((v0.z + v1.z) + (v2.z + v3.z)) + ((v4.z + v5.z) + (v6.z + v7.z));
        acc.w += ((v0.w + v1.w) + (v2.w + v3.w)) + ((v4.w + v5.w) + (v6.w + v7.w));
    }
    for (; j < end; j++) {
        int s = g1_idx[j];
        float4 v = __ldg(X4 + s * 32 + lane);
        acc.x += v.x; acc.y += v.y; acc.z += v.z; acc.w += v.w;
    }
    float de = __ldg(degE + e);
    uint2 o;
    o.x = h2_to_u32(__floats2half2_rn(acc.x * de, acc.y * de));
    o.y = h2_to_u32(__floats2half2_rn(acc.z * de, acc.w * de));
    g_XeH[e * 32 + lane] = o;
}

// ---------------------------------------------------------------------------
// SpMM 2 + residual: XiH[v] = fp16( (1-a)*degV[v]*sum XeH[s] + a*X0[v] )
// ---------------------------------------------------------------------------
__global__ void spmm2_kernel(const float4* __restrict__ X04,
                             const float* __restrict__ degV,
                             const float* __restrict__ alpha) {
    int v = (blockIdx.x * blockDim.x + threadIdx.x) >> 5;
    if (v >= N_NODES) return;
    int lane = threadIdx.x & 31;
    int beg = g2_off[v], end = g2_off[v + 1];

    float4 acc = make_float4(0.f, 0.f, 0.f, 0.f);
    int j = beg;
    for (; j + 8 <= end; j += 8) {
        int s0 = g2_idx[j],     s1 = g2_idx[j + 1], s2 = g2_idx[j + 2], s3 = g2_idx[j + 3];
        int s4 = g2_idx[j + 4], s5 = g2_idx[j + 5], s6 = g2_idx[j + 6], s7 = g2_idx[j + 7];
        uint2 r0 = g_XeH[s0 * 32 + lane];
        uint2 r1 = g_XeH[s1 * 32 + lane];
        uint2 r2 = g_XeH[s2 * 32 + lane];
        uint2 r3 = g_XeH[s3 * 32 + lane];
        uint2 r4 = g_XeH[s4 * 32 + lane];
        uint2 r5 = g_XeH[s5 * 32 + lane];
        uint2 r6 = g_XeH[s6 * 32 + lane];
        uint2 r7 = g_XeH[s7 * 32 + lane];
        acc_h(acc, r0); acc_h(acc, r1); acc_h(acc, r2); acc_h(acc, r3);
        acc_h(acc, r4); acc_h(acc, r5); acc_h(acc, r6); acc_h(acc, r7);
    }
    for (; j + 4 <= end; j += 4) {
        int s0 = g2_idx[j], s1 = g2_idx[j + 1], s2 = g2_idx[j + 2], s3 = g2_idx[j + 3];
        uint2 r0 = g_XeH[s0 * 32 + lane];
        uint2 r1 = g_XeH[s1 * 32 + lane];
        uint2 r2 = g_XeH[s2 * 32 + lane];
        uint2 r3 = g_XeH[s3 * 32 + lane];
        acc_h(acc, r0); acc_h(acc, r1); acc_h(acc, r2); acc_h(acc, r3);
    }
    for (; j < end; j++) {
        int s = g2_idx[j];
        acc_h(acc, g_XeH[s * 32 + lane]);
    }
    float a = __ldg(alpha);
    float sc = (1.f - a) * __ldg(degV + v);
    float4 x0 = __ldg(X04 + v * 32 + lane);
    float xi0 = sc * acc.x + a * x0.x;
    float xi1 = sc * acc.y + a * x0.y;
    float xi2 = sc * acc.z + a * x0.z;
    float xi3 = sc * acc.w + a * x0.w;
    uint2 o;
    o.x = h2_to_u32(__floats2half2_rn(xi0, xi1));
    o.y = h2_to_u32(__floats2half2_rn(xi2, xi3));
    g_XiH[v * 32 + lane] = o;
}

// ---------------------------------------------------------------------------
// GEMM: out = (1-b)*Xi + b*(Xi @ W^T)   (Xi fp16 in g_XiH; exact 16-row tiling)
// ---------------------------------------------------------------------------
#define XI_STRIDE 132

__global__ void __launch_bounds__(256, 2)
gemm_kernel(const float* __restrict__ beta, float* __restrict__ out) {
    __shared__ float Xism[16 * XI_STRIDE];

    const int tid = threadIdx.x;
    const int row0 = blockIdx.x * 16;
    const float bb = __ldg(beta);
    const float omb = 1.f - bb;

    const int warp = tid >> 5, lane = tid & 31;
    const int gid = lane >> 2, tig = lane & 3;
    const int nt0 = warp, nt1 = warp + 8;

    float2 bf0[16], bf1[16];
#pragma unroll
    for (int kk = 0; kk < 16; kk++) {
        bf0[kk] = __ldg(&g_Wp[(kk * 4 + tig) * 128 + nt0 * 8 + gid]);
        bf1[kk] = __ldg(&g_Wp[(kk * 4 + tig) * 128 + nt1 * 8 + gid]);
    }

    // Stage Xi tile: fp16 global -> fp32 smem
#pragma unroll
    for (int i = tid; i < 16 * 32; i += 256) {
        int r = i >> 5, c4 = i & 31;
        uint2 h = g_XiH[(row0 + r) * 32 + c4];
        float2 f0 = __half22float2(u32_to_h2(h.x));
        float2 f1 = __half22float2(u32_to_h2(h.y));
        float4 xi = make_float4(f0.x, f0.y, f1.x, f1.y);
        *reinterpret_cast<float4*>(&Xism[r * XI_STRIDE + c4 * 4]) = xi;
    }
    __syncthreads();

    float c00 = 0.f, c01 = 0.f, c02 = 0.f, c03 = 0.f;
    float c10 = 0.f, c11 = 0.f, c12 = 0.f, c13 = 0.f;

#pragma unroll
    for (int kk = 0; kk < 16; kk++) {
        int c = kk * 8 + tig;
        uint32_t a0 = f2tf32(Xism[gid * XI_STRIDE + c]);
        uint32_t a1 = f2tf32(Xism[(gid + 8) * XI_STRIDE + c]);
        uint32_t a2 = f2tf32(Xism[gid * XI_STRIDE + c + 4]);
        uint32_t a3 = f2tf32(Xism[(gid + 8) * XI_STRIDE + c + 4]);
        uint32_t b00 = __float_as_uint(bf0[kk].x);
        uint32_t b01 = __float_as_uint(bf0[kk].y);
        uint32_t b10 = __float_as_uint(bf1[kk].x);
        uint32_t b11 = __float_as_uint(bf1[kk].y);
        asm volatile(
            "mma.sync.aligned.m16n8k8.row.col.f32.tf32.tf32.f32 "
            "{%0,%1,%2,%3}, {%4,%5,%6,%7}, {%8,%9}, {%0,%1,%2,%3};"
            : "+f"(c00), "+f"(c01), "+f"(c02), "+f"(c03)
            : "r"(a0), "r"(a1), "r"(a2), "r"(a3), "r"(b00), "r"(b01));
        asm volatile(
            "mma.sync.aligned.m16n8k8.row.col.f32.tf32.tf32.f32 "
            "{%0,%1,%2,%3}, {%4,%5,%6,%7}, {%8,%9}, {%0,%1,%2,%3};"
            : "+f"(c10), "+f"(c11), "+f"(c12), "+f"(c13)
            : "r"(a0), "r"(a1), "r"(a2), "r"(a3), "r"(b10), "r"(b11));
    }

    const int r0 = row0 + gid;
    const int r1 = r0 + 8;
    {
        int col = nt0 * 8 + 2 * tig;
        float xi0 = Xism[gid * XI_STRIDE + col];
        float xi1 = Xism[gid * XI_STRIDE + col + 1];
        *reinterpret_cast<float2*>(out + (long)r0 * 128 + col) =
            make_float2(omb * xi0 + bb * c00, omb * xi1 + bb * c01);
        xi0 = Xism[(gid + 8) * XI_STRIDE + col];
        xi1 = Xism[(gid + 8) * XI_STRIDE + col + 1];
        *reinterpret_cast<float2*>(out + (long)r1 * 128 + col) =
            make_float2(omb * xi0 + bb * c02, omb * xi1 + bb * c03);

        col = nt1 * 8 + 2 * tig;
        xi0 = Xism[gid * XI_STRIDE + col];
        xi1 = Xism[gid * XI_STRIDE + col + 1];
        *reinterpret_cast<float2*>(out + (long)r0 * 128 + col) =
            make_float2(omb * xi0 + bb * c10, omb * xi1 + bb * c11);
        xi0 = Xism[(gid + 8) * XI_STRIDE + col];
        xi1 = Xism[(gid + 8) * XI_STRIDE + col + 1];
        *reinterpret_cast<float2*>(out + (long)r1 * 128 + col) =
            make_float2(omb * xi0 + bb * c12, omb * xi1 + bb * c13);
    }
}

// ---------------------------------------------------------------------------
// kernel_launch — 7 launches (scanA+scanC fused into one self-sync kernel)
// ---------------------------------------------------------------------------
extern "C" void kernel_launch(void* const* d_in, const int* in_sizes, int n_in,
                              void* d_out, int out_size) {
    const float* X     = (const float*)d_in[0];
    const float* X0    = (const float*)d_in[1];
    const float* degE  = (const float*)d_in[2];
    const float* degV  = (const float*)d_in[3];
    const float* alpha = (const float*)d_in[4];
    const float* beta  = (const float*)d_in[5];
    const float* W     = (const float*)d_in[6];
    const int*   g1s   = (const int*)d_in[7];
    const int*   g1d   = (const int*)d_in[8];
    const int*   g2s   = (const int*)d_in[9];
    const int*   g2d   = (const int*)d_in[10];
    float* out = (float*)d_out;

    // zero counters + ready flag + W prep
    prep_kernel<<<ZERO_BLKS + WPREP_BLKS, 256>>>(W);

    // CSR build: hist -> fused scan (one launch) -> fill
    hist_kernel<<<(NNZ / 4 + 255) / 256, 256>>>((const int4*)g1d, (const int4*)g2d);
    scan_fused_kernel<<<NBT, SCAN_TPB>>>();
    fill_kernel<<<(NNZ / 2 + 255) / 256, 256>>>((const int2*)g1s, (const int2*)g1d,
                                                (const int2*)g2s, (const int2*)g2d);

    // Gather-sum SpMMs (fp32 X gather; fp16 Xe and Xi intermediates)
    spmm1_kernel<<<(N_EDGES * 32 + 255) / 256, 256>>>((const float4*)X, degE);
    spmm2_kernel<<<(N_NODES * 32 + 255) / 256, 256>>>((const float4*)X0, degV, alpha);

    // tf32 GEMM + residual epilogue (100000 = 6250 * 16 exact)
    gemm_kernel<<<N_NODES / 16, 256>>>(beta, out);
}

// round 13
// speedup vs baseline: 1.0482x; 1.0271x over previous
#include <cuda_runtime.h>
#include <cuda_fp16.h>
#include <cstdint>

#define N_NODES 100000
#define N_EDGES 20000
#define NNZ     800000
#define D       128

// Scan tiling
#define SCAN_TPB   256
#define SCAN_PER   8
#define SCAN_CHUNK (SCAN_TPB * SCAN_PER)                      // 2048
#define NB1 ((N_EDGES + SCAN_CHUNK - 1) / SCAN_CHUNK)         // 10
#define NB2 ((N_NODES + SCAN_CHUNK - 1) / SCAN_CHUNK)         // 49
#define NBT (NB1 + NB2)                                       // 59

// ---------------------------------------------------------------------------
// Device-global scratch (allocation-free rule)
// ---------------------------------------------------------------------------
__device__ __align__(16) uint2 g_XeH[N_EDGES * 32]; // Xe fp16 (2x half2/lane), 5.12 MB
__device__ __align__(16) uint2 g_XiH[N_NODES * 32]; // Xi fp16, 25.6 MB
__device__ __align__(16) float2 g_Wp[64 * 128];     // packed tf32 B fragments, 64 KB

__device__ int g1_cnt[N_EDGES];
__device__ int g1_off[N_EDGES + 1];
__device__ int g1_idx[NNZ];
__device__ __align__(16) int g1_rank[NNZ];          // rank-within-destination
__device__ int g2_cnt[N_NODES];
__device__ int g2_off[N_NODES + 1];
__device__ int g2_idx[NNZ];
__device__ __align__(16) int g2_rank[NNZ];

__device__ int g_blk_sum[NBT];
__device__ int g_ready;            // reset by prep each replay

// ---------------------------------------------------------------------------
// helpers
// ---------------------------------------------------------------------------
__device__ __forceinline__ uint32_t h2_to_u32(__half2 h) {
    return *reinterpret_cast<uint32_t*>(&h);
}
__device__ __forceinline__ __half2 u32_to_h2(uint32_t u) {
    return *reinterpret_cast<__half2*>(&u);
}
__device__ __forceinline__ uint32_t f2tf32(float f) {
    uint32_t r;
    asm("cvt.rna.tf32.f32 %0, %1;" : "=r"(r) : "f"(f));
    return r;
}
__device__ __forceinline__ void acc_h(float4& acc, uint2 r) {
    float2 f0 = __half22float2(u32_to_h2(r.x));
    float2 f1 = __half22float2(u32_to_h2(r.y));
    acc.x += f0.x; acc.y += f0.y; acc.z += f1.x; acc.w += f1.y;
}

// ---------------------------------------------------------------------------
// Prep: zero counters + ready flag (blocks 0..390) + W prep (391..422)
// ---------------------------------------------------------------------------
#define ZERO_BLKS ((N_NODES + 255) / 256)        // 391
#define WPREP_BLKS 32

__global__ void prep_kernel(const float* __restrict__ W) {
    if (blockIdx.x < ZERO_BLKS) {
        int i = blockIdx.x * blockDim.x + threadIdx.x;
        if (i < N_EDGES) g1_cnt[i] = 0;
        if (i < N_NODES) g2_cnt[i] = 0;
        if (i == 0) g_ready = 0;
    } else {
        int p = (blockIdx.x - ZERO_BLKS) * blockDim.x + threadIdx.x;  // 8192 total
        if (p < 64 * 128) {
            int n = p & 127;
            int tig = (p >> 7) & 3;
            int kk = p >> 9;
            float w0 = __ldg(W + n * 128 + kk * 8 + tig);
            float w1 = __ldg(W + n * 128 + kk * 8 + tig + 4);
            float2 o;
            o.x = __uint_as_float(f2tf32(w0));
            o.y = __uint_as_float(f2tf32(w1));
            g_Wp[p] = o;
        }
    }
}

// ---------------------------------------------------------------------------
// Histogram + rank recording, both graphs (int4-vectorized).
// atomicAdd's return value IS the edge's rank within its destination bucket.
// ---------------------------------------------------------------------------
__global__ void hist_kernel(const int4* __restrict__ g1d4,
                            const int4* __restrict__ g2d4) {
    int i = blockIdx.x * blockDim.x + threadIdx.x;
    if (i >= NNZ / 4) return;
    int4 d1 = __ldg(g1d4 + i);
    int4 r1;
    r1.x = atomicAdd(&g1_cnt[d1.x], 1);
    r1.y = atomicAdd(&g1_cnt[d1.y], 1);
    r1.z = atomicAdd(&g1_cnt[d1.z], 1);
    r1.w = atomicAdd(&g1_cnt[d1.w], 1);
    reinterpret_cast<int4*>(g1_rank)[i] = r1;
    int4 d2 = __ldg(g2d4 + i);
    int4 r2;
    r2.x = atomicAdd(&g2_cnt[d2.x], 1);
    r2.y = atomicAdd(&g2_cnt[d2.y], 1);
    r2.z = atomicAdd(&g2_cnt[d2.z], 1);
    r2.w = atomicAdd(&g2_cnt[d2.w], 1);
    reinterpret_cast<int4*>(g2_rank)[i] = r2;
}

// ---------------------------------------------------------------------------
// Fused scan: single launch, 59 blocks (all co-resident; 59 < 148 SMs).
// ---------------------------------------------------------------------------
__global__ void scan_fused_kernel() {
    const int bid = blockIdx.x;
    const int t = threadIdx.x;
    const int* cnt; int* off; int n, lbase;
    if (bid < NB1) { cnt = g1_cnt; off = g1_off; n = N_EDGES; lbase = bid * SCAN_CHUNK; }
    else           { cnt = g2_cnt; off = g2_off; n = N_NODES; lbase = (bid - NB1) * SCAN_CHUNK; }

    // Phase 1: load 8 counters into registers, per-thread sum, block scan
    int c[SCAN_PER];
    int s = 0;
    const int i0 = lbase + t * SCAN_PER;
#pragma unroll
    for (int k = 0; k < SCAN_PER; k++) {
        int i = i0 + k;
        c[k] = (i < n) ? cnt[i] : 0;
        s += c[k];
    }

    const int lane = t & 31, wid = t >> 5;
    int v = s;
#pragma unroll
    for (int o = 1; o < 32; o <<= 1) {
        int u = __shfl_up_sync(0xffffffffu, v, o);
        if (lane >= o) v += u;
    }
    __shared__ int ws[8];
    if (lane == 31) ws[wid] = v;
    __syncthreads();
    if (t < 8) {
        int w = ws[t];
#pragma unroll
        for (int o = 1; o < 8; o <<= 1) {
            int u = __shfl_up_sync(0xffu, w, o);
            if (t >= o) w += u;
        }
        ws[t] = w;
    }
    __syncthreads();

    int excl = v - s + (wid ? ws[wid - 1] : 0);     // per-thread exclusive base
    if (t == SCAN_TPB - 1) {
        g_blk_sum[bid] = excl + s;
        __threadfence();
        atomicAdd(&g_ready, 1);
    }

    // Phase 2: wait for all 59 block sums
    if (t == 0) {
        volatile int* rdy = &g_ready;
        while (*rdy < NBT) { }
    }
    __syncthreads();
    __threadfence();   // acquire for g_blk_sum reads

    // Phase 3: scan the 59 sums (threads 0..63), get this block's base
    __shared__ int be[64];
    __shared__ int wtot;
    if (t < 64) {
        int bv = (t < NBT) ? g_blk_sum[t] : 0;
        int bs = bv;
#pragma unroll
        for (int o = 1; o < 32; o <<= 1) {
            int u = __shfl_up_sync(0xffffffffu, bs, o);
            if ((t & 31) >= o) bs += u;
        }
        if (t == 31) wtot = bs;
        be[t] = bs - bv;
    }
    __syncthreads();
    if (t >= 32 && t < 64) be[t] += wtot;
    __syncthreads();

    int base = be[bid] + excl;
    if (bid >= NB1) base -= NNZ;                   // g2 segment rebase
#pragma unroll
    for (int k = 0; k < SCAN_PER; k++) {
        int i = i0 + k;
        if (i < n) {
            off[i] = base;
            base += c[k];
        }
    }
    if (bid == 0 && t == 0) {
        g1_off[N_EDGES] = NNZ;
        g2_off[N_NODES] = NNZ;
    }
}

// ---------------------------------------------------------------------------
// Fill, both graphs — ATOMIC-FREE: position = off[dst] + rank (recorded in hist)
// ---------------------------------------------------------------------------
__global__ void fill_kernel(const int2* __restrict__ g1s2, const int2* __restrict__ g1d2,
                            const int2* __restrict__ g2s2, const int2* __restrict__ g2d2) {
    int i = blockIdx.x * blockDim.x + threadIdx.x;
    if (i >= NNZ / 2) return;
    int2 s1 = __ldg(g1s2 + i);
    int2 d1 = __ldg(g1d2 + i);
    int2 r1 = *reinterpret_cast<const int2*>(g1_rank + 2 * i);
    g1_idx[g1_off[d1.x] + r1.x] = s1.x;
    g1_idx[g1_off[d1.y] + r1.y] = s1.y;
    int2 s2 = __ldg(g2s2 + i);
    int2 d2 = __ldg(g2d2 + i);
    int2 r2 = *reinterpret_cast<const int2*>(g2_rank + 2 * i);
    g2_idx[g2_off[d2.x] + r2.x] = s2.x;
    g2_idx[g2_off[d2.y] + r2.y] = s2.y;
}

// ---------------------------------------------------------------------------
// SpMM 1: XeH[e] = fp16( degE[e] * sum X[s] )   (warp/edge, fp32 gather, u8)
// ---------------------------------------------------------------------------
__global__ void spmm1_kernel(const float4* __restrict__ X4,
                             const float* __restrict__ degE) {
    int e = (blockIdx.x * blockDim.x + threadIdx.x) >> 5;
    if (e >= N_EDGES) return;
    int lane = threadIdx.x & 31;
    int beg = g1_off[e], end = g1_off[e + 1];

    float4 acc = make_float4(0.f, 0.f, 0.f, 0.f);
    int j = beg;
    for (; j + 8 <= end; j += 8) {
        int s0 = g1_idx[j],     s1 = g1_idx[j + 1], s2 = g1_idx[j + 2], s3 = g1_idx[j + 3];
        int s4 = g1_idx[j + 4], s5 = g1_idx[j + 5], s6 = g1_idx[j + 6], s7 = g1_idx[j + 7];
        float4 v0 = __ldg(X4 + s0 * 32 + lane);
        float4 v1 = __ldg(X4 + s1 * 32 + lane);
        float4 v2 = __ldg(X4 + s2 * 32 + lane);
        float4 v3 = __ldg(X4 + s3 * 32 + lane);
        float4 v4 = __ldg(X4 + s4 * 32 + lane);
        float4 v5 = __ldg(X4 + s5 * 32 + lane);
        float4 v6 = __ldg(X4 + s6 * 32 + lane);
        float4 v7 = __ldg(X4 + s7 * 32 + lane);
        acc.x += ((v0.x + v1.x) + (v2.x + v3.x)) + ((v4.x + v5.x) + (v6.x + v7.x));
        acc.y += ((v0.y + v1.y) + (v2.y + v3.y)) + ((v4.y + v5.y) + (v6.y + v7.y));
        acc.z += ((v0.z + v1.z) + (v2.z + v3.z)) + ((v4.z + v5.z) + (v6.z + v7.z));
        acc.w += ((v0.w + v1.w) + (v2.w + v3.w)) + ((v4.w + v5.w) + (v6.w + v7.w));
    }
    for (; j < end; j++) {
        int s = g1_idx[j];
        float4 v = __ldg(X4 + s * 32 + lane);
        acc.x += v.x; acc.y += v.y; acc.z += v.z; acc.w += v.w;
    }
    float de = __ldg(degE + e);
    uint2 o;
    o.x = h2_to_u32(__floats2half2_rn(acc.x * de, acc.y * de));
    o.y = h2_to_u32(__floats2half2_rn(acc.z * de, acc.w * de));
    g_XeH[e * 32 + lane] = o;
}

// ---------------------------------------------------------------------------
// SpMM 2 + residual: XiH[v] = fp16( (1-a)*degV[v]*sum XeH[s] + a*X0[v] )
// ---------------------------------------------------------------------------
__global__ void spmm2_kernel(const float4* __restrict__ X04,
                             const float* __restrict__ degV,
                             const float* __restrict__ alpha) {
    int v = (blockIdx.x * blockDim.x + threadIdx.x) >> 5;
    if (v >= N_NODES) return;
    int lane = threadIdx.x & 31;
    int beg = g2_off[v], end = g2_off[v + 1];

    float4 acc = make_float4(0.f, 0.f, 0.f, 0.f);
    int j = beg;
    for (; j + 8 <= end; j += 8) {
        int s0 = g2_idx[j],     s1 = g2_idx[j + 1], s2 = g2_idx[j + 2], s3 = g2_idx[j + 3];
        int s4 = g2_idx[j + 4], s5 = g2_idx[j + 5], s6 = g2_idx[j + 6], s7 = g2_idx[j + 7];
        uint2 r0 = g_XeH[s0 * 32 + lane];
        uint2 r1 = g_XeH[s1 * 32 + lane];
        uint2 r2 = g_XeH[s2 * 32 + lane];
        uint2 r3 = g_XeH[s3 * 32 + lane];
        uint2 r4 = g_XeH[s4 * 32 + lane];
        uint2 r5 = g_XeH[s5 * 32 + lane];
        uint2 r6 = g_XeH[s6 * 32 + lane];
        uint2 r7 = g_XeH[s7 * 32 + lane];
        acc_h(acc, r0); acc_h(acc, r1); acc_h(acc, r2); acc_h(acc, r3);
        acc_h(acc, r4); acc_h(acc, r5); acc_h(acc, r6); acc_h(acc, r7);
    }
    for (; j + 4 <= end; j += 4) {
        int s0 = g2_idx[j], s1 = g2_idx[j + 1], s2 = g2_idx[j + 2], s3 = g2_idx[j + 3];
        uint2 r0 = g_XeH[s0 * 32 + lane];
        uint2 r1 = g_XeH[s1 * 32 + lane];
        uint2 r2 = g_XeH[s2 * 32 + lane];
        uint2 r3 = g_XeH[s3 * 32 + lane];
        acc_h(acc, r0); acc_h(acc, r1); acc_h(acc, r2); acc_h(acc, r3);
    }
    for (; j < end; j++) {
        int s = g2_idx[j];
        acc_h(acc, g_XeH[s * 32 + lane]);
    }
    float a = __ldg(alpha);
    float sc = (1.f - a) * __ldg(degV + v);
    float4 x0 = __ldg(X04 + v * 32 + lane);
    float xi0 = sc * acc.x + a * x0.x;
    float xi1 = sc * acc.y + a * x0.y;
    float xi2 = sc * acc.z + a * x0.z;
    float xi3 = sc * acc.w + a * x0.w;
    uint2 o;
    o.x = h2_to_u32(__floats2half2_rn(xi0, xi1));
    o.y = h2_to_u32(__floats2half2_rn(xi2, xi3));
    g_XiH[v * 32 + lane] = o;
}

// ---------------------------------------------------------------------------
// GEMM: out = (1-b)*Xi + b*(Xi @ W^T)   (Xi fp16 in g_XiH; exact 16-row tiling)
// ---------------------------------------------------------------------------
#define XI_STRIDE 132

__global__ void __launch_bounds__(256, 2)
gemm_kernel(const float* __restrict__ beta, float* __restrict__ out) {
    __shared__ float Xism[16 * XI_STRIDE];

    const int tid = threadIdx.x;
    const int row0 = blockIdx.x * 16;
    const float bb = __ldg(beta);
    const float omb = 1.f - bb;

    const int warp = tid >> 5, lane = tid & 31;
    const int gid = lane >> 2, tig = lane & 3;
    const int nt0 = warp, nt1 = warp + 8;

    float2 bf0[16], bf1[16];
#pragma unroll
    for (int kk = 0; kk < 16; kk++) {
        bf0[kk] = __ldg(&g_Wp[(kk * 4 + tig) * 128 + nt0 * 8 + gid]);
        bf1[kk] = __ldg(&g_Wp[(kk * 4 + tig) * 128 + nt1 * 8 + gid]);
    }

    // Stage Xi tile: fp16 global -> fp32 smem
#pragma unroll
    for (int i = tid; i < 16 * 32; i += 256) {
        int r = i >> 5, c4 = i & 31;
        uint2 h = g_XiH[(row0 + r) * 32 + c4];
        float2 f0 = __half22float2(u32_to_h2(h.x));
        float2 f1 = __half22float2(u32_to_h2(h.y));
        float4 xi = make_float4(f0.x, f0.y, f1.x, f1.y);
        *reinterpret_cast<float4*>(&Xism[r * XI_STRIDE + c4 * 4]) = xi;
    }
    __syncthreads();

    float c00 = 0.f, c01 = 0.f, c02 = 0.f, c03 = 0.f;
    float c10 = 0.f, c11 = 0.f, c12 = 0.f, c13 = 0.f;

#pragma unroll
    for (int kk = 0; kk < 16; kk++) {
        int c = kk * 8 + tig;
        uint32_t a0 = f2tf32(Xism[gid * XI_STRIDE + c]);
        uint32_t a1 = f2tf32(Xism[(gid + 8) * XI_STRIDE + c]);
        uint32_t a2 = f2tf32(Xism[gid * XI_STRIDE + c + 4]);
        uint32_t a3 = f2tf32(Xism[(gid + 8) * XI_STRIDE + c + 4]);
        uint32_t b00 = __float_as_uint(bf0[kk].x);
        uint32_t b01 = __float_as_uint(bf0[kk].y);
        uint32_t b10 = __float_as_uint(bf1[kk].x);
        uint32_t b11 = __float_as_uint(bf1[kk].y);
        asm volatile(
            "mma.sync.aligned.m16n8k8.row.col.f32.tf32.tf32.f32 "
            "{%0,%1,%2,%3}, {%4,%5,%6,%7}, {%8,%9}, {%0,%1,%2,%3};"
            : "+f"(c00), "+f"(c01), "+f"(c02), "+f"(c03)
            : "r"(a0), "r"(a1), "r"(a2), "r"(a3), "r"(b00), "r"(b01));
        asm volatile(
            "mma.sync.aligned.m16n8k8.row.col.f32.tf32.tf32.f32 "
            "{%0,%1,%2,%3}, {%4,%5,%6,%7}, {%8,%9}, {%0,%1,%2,%3};"
            : "+f"(c10), "+f"(c11), "+f"(c12), "+f"(c13)
            : "r"(a0), "r"(a1), "r"(a2), "r"(a3), "r"(b10), "r"(b11));
    }

    const int r0 = row0 + gid;
    const int r1 = r0 + 8;
    {
        int col = nt0 * 8 + 2 * tig;
        float xi0 = Xism[gid * XI_STRIDE + col];
        float xi1 = Xism[gid * XI_STRIDE + col + 1];
        *reinterpret_cast<float2*>(out + (long)r0 * 128 + col) =
            make_float2(omb * xi0 + bb * c00, omb * xi1 + bb * c01);
        xi0 = Xism[(gid + 8) * XI_STRIDE + col];
        xi1 = Xism[(gid + 8) * XI_STRIDE + col + 1];
        *reinterpret_cast<float2*>(out + (long)r1 * 128 + col) =
            make_float2(omb * xi0 + bb * c02, omb * xi1 + bb * c03);

        col = nt1 * 8 + 2 * tig;
        xi0 = Xism[gid * XI_STRIDE + col];
        xi1 = Xism[gid * XI_STRIDE + col + 1];
        *reinterpret_cast<float2*>(out + (long)r0 * 128 + col) =
            make_float2(omb * xi0 + bb * c10, omb * xi1 + bb * c11);
        xi0 = Xism[(gid + 8) * XI_STRIDE + col];
        xi1 = Xism[(gid + 8) * XI_STRIDE + col + 1];
        *reinterpret_cast<float2*>(out + (long)r1 * 128 + col) =
            make_float2(omb * xi0 + bb * c12, omb * xi1 + bb * c13);
    }
}

// ---------------------------------------------------------------------------
// kernel_launch — 7 launches; fill is now atomic-free (rank-recording hist)
// ---------------------------------------------------------------------------
extern "C" void kernel_launch(void* const* d_in, const int* in_sizes, int n_in,
                              void* d_out, int out_size) {
    const float* X     = (const float*)d_in[0];
    const float* X0    = (const float*)d_in[1];
    const float* degE  = (const float*)d_in[2];
    const float* degV  = (const float*)d_in[3];
    const float* alpha = (const float*)d_in[4];
    const float* beta  = (const float*)d_in[5];
    const float* W     = (const float*)d_in[6];
    const int*   g1s   = (const int*)d_in[7];
    const int*   g1d   = (const int*)d_in[8];
    const int*   g2s   = (const int*)d_in[9];
    const int*   g2d   = (const int*)d_in[10];
    float* out = (float*)d_out;

    // zero counters + ready flag + W prep
    prep_kernel<<<ZERO_BLKS + WPREP_BLKS, 256>>>(W);

    // CSR build: rank-recording hist -> fused scan -> atomic-free fill
    hist_kernel<<<(NNZ / 4 + 255) / 256, 256>>>((const int4*)g1d, (const int4*)g2d);
    scan_fused_kernel<<<NBT, SCAN_TPB>>>();
    fill_kernel<<<(NNZ / 2 + 255) / 256, 256>>>((const int2*)g1s, (const int2*)g1d,
                                                (const int2*)g2s, (const int2*)g2d);

    // Gather-sum SpMMs (fp32 X gather; fp16 Xe and Xi intermediates)
    spmm1_kernel<<<(N_EDGES * 32 + 255) / 256, 256>>>((const float4*)X, degE);
    spmm2_kernel<<<(N_NODES * 32 + 255) / 256, 256>>>((const float4*)X0, degV, alpha);

    // tf32 GEMM + residual epilogue (100000 = 6250 * 16 exact)
    gemm_kernel<<<N_NODES / 16, 256>>>(beta, out);
}